// round 8
// baseline (speedup 1.0000x reference)
#include <cuda_runtime.h>
#include <math_constants.h>

// Problem constants (fixed by setup_inputs): B=8, N=128, H=256, F=1023
#define B_ 8
#define N_ 128
#define H_ 256

#define BM 32
#define BN 32
#define BK 128
#define RSTR 132   // row stride (floats) = 528B = 33*16B: rows 0..7 hit
                   // distinct 16B bank groups for LDS.128

// Scratch: per-(row, j-tile) partial argmax + completion counter
__device__ float g_pval[B_ * N_ * 4];
__device__ int   g_pidx[B_ * N_ * 4];
__device__ int   g_cnt;          // zero-initialized; last block resets to 0

// ---------------------------------------------------------------------------
// Fused kernel, 512 threads, 128 blocks (one 32x32 logits tile each).
//   prologue: r_i = x_i.W0 + bias, s_j = x_j.W1            (rs smem)
//   2 passes of BK=128: load As[i][k]=Xi, Bs[j][k]=Xj*W2 (row-major),
//     each k-half (256 thr) computes its 64 k of the pass via LDS.128,
//     2x2 microtile, 8 accumulator chains.
//   combine: half-1 accs through smem; half 0 epilogue:
//     logits + r_i + s_j + W3[j+127-a(b,i)] + mask, store,
//     16-lane partial argmax -> scratch; last block decodes preds.
// ---------------------------------------------------------------------------
__global__ void __launch_bounds__(512)
pair_fused_kernel(const float* __restrict__ x,
                  const int* __restrict__ mask,
                  const float* __restrict__ W,
                  const float* __restrict__ bias,
                  float* __restrict__ out,
                  float* __restrict__ preds) {
    __shared__ __align__(16) float As[BM * RSTR];   // 16.9 KB
    __shared__ __align__(16) float Bs[BN * RSTR];   // 16.9 KB (W2 folded)
    __shared__ float rs[64];              // [0:32) r_i(+bias), [32:64) s_j
    __shared__ float red[256 * 5];        // half-1 partial accs (stride 5)

    const int t  = threadIdx.x;
    const int h  = t >> 8;                // k-half 0/1
    const int t2 = t & 255;
    const int jt = blockIdx.x, it = blockIdx.y, bb = blockIdx.z;
    const int i0 = it * BM, j0 = jt * BN;
    const float* xb = x + bb * N_ * H_;
    const float* W2 = W + 2 * H_;

    // ---- prologue: row dots (64 rows x 8 threads, 32 floats each) ---------
    {
        const int pr  = t >> 3;           // 0..63
        const int oct = t & 7;            // k-octant
        const int grow = (pr < 32) ? (i0 + pr) : (j0 + (pr - 32));
        const float* xr = xb + grow * H_ + oct * 32;
        const float* wr = W + ((pr < 32) ? 0 : H_) + oct * 32;
        float sum = 0.f;
#pragma unroll
        for (int q = 0; q < 8; q++) {
            float4 xv = ((const float4*)xr)[q];
            float4 wv = ((const float4*)wr)[q];
            sum += xv.x * wv.x + xv.y * wv.y + xv.z * wv.z + xv.w * wv.w;
        }
        sum += __shfl_xor_sync(0xffffffffu, sum, 1);
        sum += __shfl_xor_sync(0xffffffffu, sum, 2);
        sum += __shfl_xor_sync(0xffffffffu, sum, 4);
        if (oct == 0) rs[pr] = sum + ((pr < 32) ? bias[0] : 0.f);
    }

    // ---- main GEMM: 2 passes of BK=128, split-K halves --------------------
    const int ig = t2 >> 4;               // 0..15 -> rows ig*2, ig*2+1
    const int jg = t2 & 15;               // 0..15 -> cols jg*2, jg*2+1
    const int lrow = t >> 3;              // loader row 0..63
    const int lseg = t & 7;               // loader 16-float k segment

    // 8 accumulator chains: [m][n][parity(xy/zw)]
    float a00x = 0.f, a00z = 0.f, a01x = 0.f, a01z = 0.f;
    float a10x = 0.f, a10z = 0.f, a11x = 0.f, a11z = 0.f;

#pragma unroll
    for (int pass = 0; pass < 2; pass++) {
        const int k0 = pass * BK;
        __syncthreads();                  // tile reuse guard (and prologue)
        // load: rows 0..31 -> As, rows 32..63 -> Bs (warp-uniform branch)
        if (lrow < 32) {
            const float* src = xb + (i0 + lrow) * H_ + k0 + lseg * 16;
            float* dst = As + lrow * RSTR + lseg * 16;
#pragma unroll
            for (int q = 0; q < 4; q++)
                ((float4*)dst)[q] = ((const float4*)src)[q];
        } else {
            const int br = lrow - 32;
            const float* src = xb + (j0 + br) * H_ + k0 + lseg * 16;
            const float* wsrc = W2 + k0 + lseg * 16;
            float* dst = Bs + br * RSTR + lseg * 16;
#pragma unroll
            for (int q = 0; q < 4; q++) {
                float4 v = ((const float4*)src)[q];
                float4 wv = ((const float4*)wsrc)[q];
                ((float4*)dst)[q] = make_float4(v.x * wv.x, v.y * wv.y,
                                                v.z * wv.z, v.w * wv.w);
            }
        }
        __syncthreads();

        // compute this pass's k-half: 64 k in 16 float4 steps
        const float4* ap0 = (const float4*)(As + (ig * 2 + 0) * RSTR + h * 64);
        const float4* ap1 = (const float4*)(As + (ig * 2 + 1) * RSTR + h * 64);
        const float4* bp0 = (const float4*)(Bs + (jg * 2 + 0) * RSTR + h * 64);
        const float4* bp1 = (const float4*)(Bs + (jg * 2 + 1) * RSTR + h * 64);
#pragma unroll
        for (int q = 0; q < 16; q++) {
            float4 av0 = ap0[q];
            float4 av1 = ap1[q];
            float4 bv0 = bp0[q];
            float4 bv1 = bp1[q];
            a00x += av0.x * bv0.x + av0.y * bv0.y;
            a00z += av0.z * bv0.z + av0.w * bv0.w;
            a01x += av0.x * bv1.x + av0.y * bv1.y;
            a01z += av0.z * bv1.z + av0.w * bv1.w;
            a10x += av1.x * bv0.x + av1.y * bv0.y;
            a10z += av1.z * bv0.z + av1.w * bv0.w;
            a11x += av1.x * bv1.x + av1.y * bv1.y;
            a11z += av1.z * bv1.z + av1.w * bv1.w;
        }
    }

    const float acc00 = a00x + a00z;
    const float acc01 = a01x + a01z;
    const float acc10 = a10x + a10z;
    const float acc11 = a11x + a11z;

    // ---- combine k-halves --------------------------------------------------
    __syncthreads();
    if (h == 1) {
        float* dst = red + t2 * 5;        // stride 5: conflict-free
        dst[0] = acc00; dst[1] = acc01; dst[2] = acc10; dst[3] = acc11;
    }
    __syncthreads();

    // ---- epilogue (half 0 only) -------------------------------------------
    if (h == 0) {
        const float* src = red + t2 * 5;
        const float* W3 = W + 3 * H_;
        const int* mb = mask + bb * N_;
        const float sj0 = rs[32 + jg * 2 + 0];
        const float sj1 = rs[32 + jg * 2 + 1];

        float am[2][2] = {{acc00 + src[0], acc01 + src[1]},
                          {acc10 + src[2], acc11 + src[3]}};

#pragma unroll
        for (int m = 0; m < 2; m++) {
            const int li = ig * 2 + m;
            const int i  = i0 + li;
            // repeat_interleave(dim=0).view quirk: one-hot row = (b*128+i)//8
            const int aidx = bb * 16 + (i >> 3);
            const float ri = rs[li];
            const bool mi = mb[i] != 0;

            float v[2];
#pragma unroll
            for (int n = 0; n < 2; n++) {
                const int j = j0 + jg * 2 + n;
                float vv = am[m][n] + ri + ((n == 0) ? sj0 : sj1)
                         + W3[j + 127 - aidx];
                if (!(mi && (mb[j] != 0))) vv = -CUDART_INF_F;
                v[n] = vv;
            }
            *(float2*)(out + (bb * N_ + i) * N_ + j0 + jg * 2)
                = make_float2(v[0], v[1]);

            // partial argmax over tile's 32 cols (first-occurrence ties)
            float best = v[0];
            int   bj   = j0 + jg * 2;
            if (v[1] > best) { best = v[1]; bj = j0 + jg * 2 + 1; }
#pragma unroll
            for (int off = 8; off; off >>= 1) {
                float ov = __shfl_down_sync(0xffffffffu, best, off, 16);
                int   oj = __shfl_down_sync(0xffffffffu, bj,   off, 16);
                if (ov > best || (ov == best && oj < bj)) { best = ov; bj = oj; }
            }
            if (jg == 0) {
                g_pval[(bb * N_ + i) * 4 + jt] = best;
                g_pidx[(bb * N_ + i) * 4 + jt] = bj;
            }
        }
    }

    // ---- last-arriving block decodes preds --------------------------------
    __threadfence();                       // publish partials before counter
    __syncthreads();
    __shared__ int slast;
    if (t == 0) slast = atomicAdd(&g_cnt, 1);
    __syncthreads();
    if (slast == gridDim.x * gridDim.y * gridDim.z - 1) {
        for (int r = t; r < B_ * N_; r += 512) {
            float bv = g_pval[r * 4 + 0];
            int   bj = g_pidx[r * 4 + 0];
#pragma unroll
            for (int q = 1; q < 4; q++) {
                float v = g_pval[r * 4 + q];
                if (v > bv) { bv = v; bj = g_pidx[r * 4 + q]; }  // idx grows with q
            }
            preds[r] = (float)bj;
        }
        __syncthreads();
        if (t == 0) g_cnt = 0;   // reset for next graph replay
    }
}

// ---------------------------------------------------------------------------
extern "C" void kernel_launch(void* const* d_in, const int* in_sizes, int n_in,
                              void* d_out, int out_size) {
    const float* x    = (const float*)d_in[0];   // [8,128,256] float32
    const int*   mask = (const int*)d_in[1];     // [8,128] bool -> int32
    const float* W    = (const float*)d_in[2];   // [1,1023] float32
    const float* bias = (const float*)d_in[3];   // [1] float32
    float* out = (float*)d_out;

    const int nlog = B_ * N_ * N_;               // 131072
    float* preds = out + nlog;                   // [1024] as float

    dim3 grid(N_ / BN, N_ / BM, B_);             // (4,4,8) = 128 blocks
    pair_fused_kernel<<<grid, 512>>>(x, mask, W, bias, out, preds);
}

// round 9
// speedup vs baseline: 1.2573x; 1.2573x over previous
#include <cuda_runtime.h>
#include <math_constants.h>

// Problem constants (fixed by setup_inputs): B=8, N=128, H=256, F=1023
#define B_ 8
#define N_ 128
#define H_ 256

#define BM 32
#define BN 32
#define BK 128
#define KSTR 36    // k-major row stride (floats) = 144B = 9*16B: float4-aligned,
                   // bank shift 4/row; frag reads are conflict-free (see below)

// Scratch: per-(row, j-tile) partial argmax + completion counter
__device__ float g_pval[B_ * N_ * 4];
__device__ int   g_pidx[B_ * N_ * 4];
__device__ int   g_cnt;          // zero-initialized; last block resets to 0

// ---------------------------------------------------------------------------
// Fused kernel, 256 threads, 128 blocks (one 32x32 logits tile each).
//   prologue: r_i = x_i.W0 + bias, s_j = x_j.W1      (rs smem; warms L1)
//   2 passes of BK=128: load k-major As[k][i]=Xi, Bs[k][j]=Xj*W2,
//     4 split-K groups of 64 threads (8x8), each thread a 4x4 microtile:
//     per k: 2 LDS.128 (A-frag bcast 1 wf, B-frag 1 wf) + 16 FFMA.
//   reduce:  groups 1-3 write accs into As region (overlay); group 0 adds,
//   epilogue: + r_i + s_j + W3[j+127-a(b,i)], mask, store float4,
//     width-8 partial argmax -> scratch; last block decodes preds.
// ---------------------------------------------------------------------------
__global__ void __launch_bounds__(256)
pair_fused_kernel(const float* __restrict__ x,
                  const int* __restrict__ mask,
                  const float* __restrict__ W,
                  const float* __restrict__ bias,
                  float* __restrict__ out,
                  float* __restrict__ preds) {
    __shared__ __align__(16) float As[BK * KSTR];   // 18.4 KB (k-major)
    __shared__ __align__(16) float Bs[BK * KSTR];   // 18.4 KB (W2 folded)
    __shared__ float rs[64];              // [0:32) r_i(+bias), [32:64) s_j

    const int t  = threadIdx.x;
    const int g  = t >> 6;                // split-K group 0..3
    const int ts = t & 63;
    const int ig = ts >> 3;               // 0..7 -> rows ig*4..ig*4+3
    const int jg = ts & 7;                // 0..7 -> cols jg*4..jg*4+3
    const int jt = blockIdx.x, it = blockIdx.y, bb = blockIdx.z;
    const int i0 = it * BM, j0 = jt * BN;
    const float* xb = x + bb * N_ * H_;
    const float* W2 = W + 2 * H_;

    // ---- prologue: row dots (64 rows x 4 threads, 64 floats each) ---------
    {
        const int pr = t >> 2;            // 0..63
        const int qt = t & 3;             // k-quarter
        const int grow = (pr < 32) ? (i0 + pr) : (j0 + (pr - 32));
        const float* xr = xb + grow * H_ + qt * 64;
        const float* wr = W + ((pr < 32) ? 0 : H_) + qt * 64;
        float sum = 0.f;
#pragma unroll
        for (int q = 0; q < 16; q++) {
            float4 xv = ((const float4*)xr)[q];
            float4 wv = ((const float4*)wr)[q];
            sum += xv.x * wv.x + xv.y * wv.y + xv.z * wv.z + xv.w * wv.w;
        }
        sum += __shfl_xor_sync(0xffffffffu, sum, 1);
        sum += __shfl_xor_sync(0xffffffffu, sum, 2);
        if (qt == 0) rs[pr] = sum + ((pr < 32) ? bias[0] : 0.f);
    }

    // ---- main GEMM: 2 passes of BK=128, 4-way split-K ---------------------
    const int lrow = t & 31;              // loader row 0..31 (lane id)
    const int lkq  = t >> 5;              // loader k-16-segment 0..7 (warp id)

    float4 acc0 = {0.f,0.f,0.f,0.f}, acc1 = {0.f,0.f,0.f,0.f};
    float4 acc2 = {0.f,0.f,0.f,0.f}, acc3 = {0.f,0.f,0.f,0.f};

#pragma unroll
    for (int pass = 0; pass < 2; pass++) {
        const int k0 = pass * BK;
        __syncthreads();                  // tile reuse guard (and prologue)

        // load A rows (32 x BK) and B rows (W2 folded), k-major scatter.
        // STS banks: (k*36 + row) mod 32 = (4k + row) mod 32, row=lane ->
        // all 32 distinct: conflict-free scalar stores.
        {
            const float* asrc = xb + (i0 + lrow) * H_ + k0 + lkq * 16;
            const float* bsrc = xb + (j0 + lrow) * H_ + k0 + lkq * 16;
            const float* wsrc = W2 + k0 + lkq * 16;
#pragma unroll
            for (int q = 0; q < 4; q++) {
                float4 av = ((const float4*)asrc)[q];
                float4 bv = ((const float4*)bsrc)[q];
                float4 wv = ((const float4*)wsrc)[q];
                const int k = lkq * 16 + q * 4;
                As[(k + 0) * KSTR + lrow] = av.x;
                As[(k + 1) * KSTR + lrow] = av.y;
                As[(k + 2) * KSTR + lrow] = av.z;
                As[(k + 3) * KSTR + lrow] = av.w;
                Bs[(k + 0) * KSTR + lrow] = bv.x * wv.x;
                Bs[(k + 1) * KSTR + lrow] = bv.y * wv.y;
                Bs[(k + 2) * KSTR + lrow] = bv.z * wv.z;
                Bs[(k + 3) * KSTR + lrow] = bv.w * wv.w;
            }
        }
        __syncthreads();

        // compute: group g covers tile-k [g*32, g*32+32)
        const float* ap = As + (g * 32) * KSTR + ig * 4;
        const float* bp = Bs + (g * 32) * KSTR + jg * 4;
#pragma unroll
        for (int kk = 0; kk < 32; kk++) {
            float4 af = *(const float4*)(ap + kk * KSTR);
            float4 bf = *(const float4*)(bp + kk * KSTR);
            acc0.x += af.x * bf.x; acc0.y += af.x * bf.y;
            acc0.z += af.x * bf.z; acc0.w += af.x * bf.w;
            acc1.x += af.y * bf.x; acc1.y += af.y * bf.y;
            acc1.z += af.y * bf.z; acc1.w += af.y * bf.w;
            acc2.x += af.z * bf.x; acc2.y += af.z * bf.y;
            acc2.z += af.z * bf.z; acc2.w += af.z * bf.w;
            acc3.x += af.w * bf.x; acc3.y += af.w * bf.y;
            acc3.z += af.w * bf.z; acc3.w += af.w * bf.w;
        }
    }

    // ---- split-K reduction through As overlay -----------------------------
    __syncthreads();                      // all reads of As/Bs done
    if (g != 0) {
        float4* dst = (float4*)(As + ((g - 1) * 64 + ts) * 20);  // 20 = 5*f4
        dst[0] = acc0; dst[1] = acc1; dst[2] = acc2; dst[3] = acc3;
    }
    __syncthreads();

    // ---- epilogue (group 0: 64 threads, 16 outputs each) ------------------
    if (g == 0) {
#pragma unroll
        for (int q = 1; q < 4; q++) {
            const float4* src = (const float4*)(As + ((q - 1) * 64 + ts) * 20);
            float4 p0 = src[0], p1 = src[1], p2 = src[2], p3 = src[3];
            acc0.x += p0.x; acc0.y += p0.y; acc0.z += p0.z; acc0.w += p0.w;
            acc1.x += p1.x; acc1.y += p1.y; acc1.z += p1.z; acc1.w += p1.w;
            acc2.x += p2.x; acc2.y += p2.y; acc2.z += p2.z; acc2.w += p2.w;
            acc3.x += p3.x; acc3.y += p3.y; acc3.z += p3.z; acc3.w += p3.w;
        }

        const float* W3 = W + 3 * H_;
        const int* mb = mask + bb * N_;
        const int jb = j0 + jg * 4;
        const float4 sj = *(const float4*)(rs + 32 + jg * 4);
        const bool mj0 = mb[jb + 0] != 0, mj1 = mb[jb + 1] != 0;
        const bool mj2 = mb[jb + 2] != 0, mj3 = mb[jb + 3] != 0;

        float4 rowacc[4] = {acc0, acc1, acc2, acc3};
#pragma unroll
        for (int m = 0; m < 4; m++) {
            const int li = ig * 4 + m;
            const int i  = i0 + li;
            // repeat_interleave(dim=0).view quirk: one-hot row = (b*128+i)//8
            const int aidx = bb * 16 + (i >> 3);
            const float ri = rs[li];
            const bool mi = mb[i] != 0;
            const float* w3r = W3 + 127 - aidx + jb;

            float v0 = rowacc[m].x + ri + sj.x + w3r[0];
            float v1 = rowacc[m].y + ri + sj.y + w3r[1];
            float v2 = rowacc[m].z + ri + sj.z + w3r[2];
            float v3 = rowacc[m].w + ri + sj.w + w3r[3];
            if (!(mi && mj0)) v0 = -CUDART_INF_F;
            if (!(mi && mj1)) v1 = -CUDART_INF_F;
            if (!(mi && mj2)) v2 = -CUDART_INF_F;
            if (!(mi && mj3)) v3 = -CUDART_INF_F;
            *(float4*)(out + (bb * N_ + i) * N_ + jb)
                = make_float4(v0, v1, v2, v3);

            // partial argmax over tile's 32 cols (first-occurrence ties)
            float best = v0; int bj = jb;
            if (v1 > best) { best = v1; bj = jb + 1; }
            if (v2 > best) { best = v2; bj = jb + 2; }
            if (v3 > best) { best = v3; bj = jb + 3; }
#pragma unroll
            for (int off = 4; off; off >>= 1) {
                float ov = __shfl_down_sync(0xffffffffu, best, off, 8);
                int   oj = __shfl_down_sync(0xffffffffu, bj,   off, 8);
                if (ov > best || (ov == best && oj < bj)) { best = ov; bj = oj; }
            }
            if (jg == 0) {
                g_pval[(bb * N_ + i) * 4 + jt] = best;
                g_pidx[(bb * N_ + i) * 4 + jt] = bj;
            }
        }
    }

    // ---- last-arriving block decodes preds --------------------------------
    __threadfence();                       // publish partials before counter
    __syncthreads();
    __shared__ int slast;
    if (t == 0) slast = atomicAdd(&g_cnt, 1);
    __syncthreads();
    if (slast == gridDim.x * gridDim.y * gridDim.z - 1) {
        for (int r = t; r < B_ * N_; r += 256) {
            float bv = g_pval[r * 4 + 0];
            int   bj = g_pidx[r * 4 + 0];
#pragma unroll
            for (int q = 1; q < 4; q++) {
                float v = g_pval[r * 4 + q];
                if (v > bv) { bv = v; bj = g_pidx[r * 4 + q]; }  // idx grows with q
            }
            preds[r] = (float)bj;
        }
        __syncthreads();
        if (t == 0) g_cnt = 0;   // reset for next graph replay
    }
}

// ---------------------------------------------------------------------------
extern "C" void kernel_launch(void* const* d_in, const int* in_sizes, int n_in,
                              void* d_out, int out_size) {
    const float* x    = (const float*)d_in[0];   // [8,128,256] float32
    const int*   mask = (const int*)d_in[1];     // [8,128] bool -> int32
    const float* W    = (const float*)d_in[2];   // [1,1023] float32
    const float* bias = (const float*)d_in[3];   // [1] float32
    float* out = (float*)d_out;

    const int nlog = B_ * N_ * N_;               // 131072
    float* preds = out + nlog;                   // [1024] as float

    dim3 grid(N_ / BN, N_ / BM, B_);             // (4,4,8) = 128 blocks
    pair_fused_kernel<<<grid, 256>>>(x, mask, W, bias, out, preds);
}

// round 10
// speedup vs baseline: 1.5617x; 1.2421x over previous
#include <cuda_runtime.h>
#include <math_constants.h>

// Problem constants (fixed by setup_inputs): B=8, N=128, H=256, F=1023
#define B_ 8
#define N_ 128
#define H_ 256

#define BM 32
#define BN 32
#define BK 128
#define KSTR 36    // k-major row stride (floats) = 144B = 9*16B: float4-aligned;
                   // frag reads: addr16 = 9k + ig/jg -> conflict-free

// Scratch: per-(row, j-tile) partial argmax + completion counter
__device__ float g_pval[B_ * N_ * 4];
__device__ int   g_pidx[B_ * N_ * 4];
__device__ int   g_cnt;          // zero-initialized; last block resets to 0

// ---------------------------------------------------------------------------
// Fused kernel, 256 threads, 128 blocks (one 32x32 logits tile each).
//   load (per BK=128 pass): warps 0-3 -> A rows (Xi), warps 4-7 -> B rows
//     (Xj*W2), 4 lanes per row over 64B-contiguous k-quads (coalesced, nL=8).
//     Row-dots r_i = Xi.W0 / s_j = Xj.W1 fused into the loader registers,
//     reduced with width-4 shuffles (no separate prologue phase).
//   compute: 4 split-K groups of 64 threads (8x8), 4x4 microtile:
//     per k: 2 LDS.128 (1 wavefront each) + 16 FFMA.
//   reduce:  groups 1-3 write accs into As overlay; group 0 adds;
//   epilogue: + r_i + bias + s_j + W3[j+127-a(b,i)], mask, float4 store,
//     width-8 partial argmax -> scratch; last block decodes preds.
// ---------------------------------------------------------------------------
__global__ void __launch_bounds__(256)
pair_fused_kernel(const float* __restrict__ x,
                  const int* __restrict__ mask,
                  const float* __restrict__ W,
                  const float* __restrict__ bias,
                  float* __restrict__ out,
                  float* __restrict__ preds) {
    __shared__ __align__(16) float As[BK * KSTR];   // 18.4 KB (k-major)
    __shared__ __align__(16) float Bs[BK * KSTR];   // 18.4 KB (W2 folded)
    __shared__ float rs[64];              // [0:32) r_i, [32:64) s_j

    const int t  = threadIdx.x;
    const int w  = t >> 5, l = t & 31;
    const int g  = t >> 6;                // split-K group 0..3
    const int ts = t & 63;
    const int ig = ts >> 3;               // 0..7 -> rows ig*4..ig*4+3
    const int jg = ts & 7;                // 0..7 -> cols jg*4..jg*4+3
    const int jt = blockIdx.x, it = blockIdx.y, bb = blockIdx.z;
    const int i0 = it * BM, j0 = jt * BN;
    const float* xb = x + bb * N_ * H_;
    const float* W2 = W + 2 * H_;

    // loader geometry: warp-uniform A/B split, 8 rows/warp, 4 lanes/row
    const bool isA  = (w < 4);
    const int  rowl = ((w & 3) << 3) + (l >> 2);   // 0..31
    const int  kq   = (l & 3) << 2;                // 0,4,8,12
    const int  grow = (isA ? i0 : j0) + rowl;
    const float* wdot = (isA ? W : W + H_);        // W0 or W1

    float rdot = 0.f;                     // fused row-dot partial

    float4 acc0 = {0.f,0.f,0.f,0.f}, acc1 = {0.f,0.f,0.f,0.f};
    float4 acc2 = {0.f,0.f,0.f,0.f}, acc3 = {0.f,0.f,0.f,0.f};

#pragma unroll
    for (int pass = 0; pass < 2; pass++) {
        const int k0 = pass * BK;
        __syncthreads();                  // tile reuse guard

        // ---- load + fold W2 + fused row-dot -------------------------------
        {
            const float* src  = xb + grow * H_ + k0 + kq;
            const float* wsrc = wdot + k0 + kq;
            const float* w2s  = W2 + k0 + kq;
            if (isA) {
#pragma unroll
                for (int q = 0; q < 8; q++) {
                    float4 v  = *(const float4*)(src + q * 16);
                    float4 wv = *(const float4*)(wsrc + q * 16);
                    rdot += v.x * wv.x + v.y * wv.y + v.z * wv.z + v.w * wv.w;
                    const int k = kq + q * 16;
                    As[(k + 0) * KSTR + rowl] = v.x;
                    As[(k + 1) * KSTR + rowl] = v.y;
                    As[(k + 2) * KSTR + rowl] = v.z;
                    As[(k + 3) * KSTR + rowl] = v.w;
                }
            } else {
#pragma unroll
                for (int q = 0; q < 8; q++) {
                    float4 v  = *(const float4*)(src + q * 16);
                    float4 wv = *(const float4*)(wsrc + q * 16);
                    float4 w2 = *(const float4*)(w2s + q * 16);
                    rdot += v.x * wv.x + v.y * wv.y + v.z * wv.z + v.w * wv.w;
                    const int k = kq + q * 16;
                    Bs[(k + 0) * KSTR + rowl] = v.x * w2.x;
                    Bs[(k + 1) * KSTR + rowl] = v.y * w2.y;
                    Bs[(k + 2) * KSTR + rowl] = v.z * w2.z;
                    Bs[(k + 3) * KSTR + rowl] = v.w * w2.w;
                }
            }
        }
        __syncthreads();

        // ---- compute: group g covers tile-k [g*32, g*32+32) ---------------
        const float* ap = As + (g * 32) * KSTR + ig * 4;
        const float* bp = Bs + (g * 32) * KSTR + jg * 4;
#pragma unroll
        for (int kk = 0; kk < 32; kk++) {
            float4 af = *(const float4*)(ap + kk * KSTR);
            float4 bf = *(const float4*)(bp + kk * KSTR);
            acc0.x += af.x * bf.x; acc0.y += af.x * bf.y;
            acc0.z += af.x * bf.z; acc0.w += af.x * bf.w;
            acc1.x += af.y * bf.x; acc1.y += af.y * bf.y;
            acc1.z += af.y * bf.z; acc1.w += af.y * bf.w;
            acc2.x += af.z * bf.x; acc2.y += af.z * bf.y;
            acc2.z += af.z * bf.z; acc2.w += af.z * bf.w;
            acc3.x += af.w * bf.x; acc3.y += af.w * bf.y;
            acc3.z += af.w * bf.z; acc3.w += af.w * bf.w;
        }
    }

    // ---- finalize fused row-dots (width-4 shuffle, deterministic) ---------
    rdot += __shfl_down_sync(0xffffffffu, rdot, 1, 4);
    rdot += __shfl_down_sync(0xffffffffu, rdot, 2, 4);
    if ((l & 3) == 0) rs[(isA ? 0 : 32) + rowl] = rdot;

    // ---- split-K reduction through As overlay -----------------------------
    __syncthreads();                      // all As/Bs reads + rs writes done
    if (g != 0) {
        float4* dst = (float4*)(As + ((g - 1) * 64 + ts) * 20);  // 20 = 5*f4
        dst[0] = acc0; dst[1] = acc1; dst[2] = acc2; dst[3] = acc3;
    }
    __syncthreads();

    // ---- epilogue (group 0: 64 threads, 16 outputs each) ------------------
    if (g == 0) {
#pragma unroll
        for (int q = 1; q < 4; q++) {
            const float4* src = (const float4*)(As + ((q - 1) * 64 + ts) * 20);
            float4 p0 = src[0], p1 = src[1], p2 = src[2], p3 = src[3];
            acc0.x += p0.x; acc0.y += p0.y; acc0.z += p0.z; acc0.w += p0.w;
            acc1.x += p1.x; acc1.y += p1.y; acc1.z += p1.z; acc1.w += p1.w;
            acc2.x += p2.x; acc2.y += p2.y; acc2.z += p2.z; acc2.w += p2.w;
            acc3.x += p3.x; acc3.y += p3.y; acc3.z += p3.z; acc3.w += p3.w;
        }

        const float  b0v = bias[0];
        const float* W3 = W + 3 * H_;
        const int* mb = mask + bb * N_;
        const int jb = j0 + jg * 4;
        const float4 sj = *(const float4*)(rs + 32 + jg * 4);
        const bool mj0 = mb[jb + 0] != 0, mj1 = mb[jb + 1] != 0;
        const bool mj2 = mb[jb + 2] != 0, mj3 = mb[jb + 3] != 0;

        float4 rowacc[4] = {acc0, acc1, acc2, acc3};
#pragma unroll
        for (int m = 0; m < 4; m++) {
            const int li = ig * 4 + m;
            const int i  = i0 + li;
            // repeat_interleave(dim=0).view quirk: one-hot row = (b*128+i)//8
            const int aidx = bb * 16 + (i >> 3);
            const float ri = rs[li] + b0v;
            const bool mi = mb[i] != 0;
            const float* w3r = W3 + 127 - aidx + jb;

            float v0 = rowacc[m].x + ri + sj.x + w3r[0];
            float v1 = rowacc[m].y + ri + sj.y + w3r[1];
            float v2 = rowacc[m].z + ri + sj.z + w3r[2];
            float v3 = rowacc[m].w + ri + sj.w + w3r[3];
            if (!(mi && mj0)) v0 = -CUDART_INF_F;
            if (!(mi && mj1)) v1 = -CUDART_INF_F;
            if (!(mi && mj2)) v2 = -CUDART_INF_F;
            if (!(mi && mj3)) v3 = -CUDART_INF_F;
            *(float4*)(out + (bb * N_ + i) * N_ + jb)
                = make_float4(v0, v1, v2, v3);

            // partial argmax over tile's 32 cols (first-occurrence ties)
            float best = v0; int bj = jb;
            if (v1 > best) { best = v1; bj = jb + 1; }
            if (v2 > best) { best = v2; bj = jb + 2; }
            if (v3 > best) { best = v3; bj = jb + 3; }
#pragma unroll
            for (int off = 4; off; off >>= 1) {
                float ov = __shfl_down_sync(0xffffffffu, best, off, 8);
                int   oj = __shfl_down_sync(0xffffffffu, bj,   off, 8);
                if (ov > best || (ov == best && oj < bj)) { best = ov; bj = oj; }
            }
            if (jg == 0) {
                g_pval[(bb * N_ + i) * 4 + jt] = best;
                g_pidx[(bb * N_ + i) * 4 + jt] = bj;
            }
        }
    }

    // ---- last-arriving block decodes preds --------------------------------
    if (g == 0 && jg == 0) __threadfence();   // only scratch writers fence
    __syncthreads();
    __shared__ int slast;
    if (t == 0) slast = atomicAdd(&g_cnt, 1);
    __syncthreads();
    if (slast == gridDim.x * gridDim.y * gridDim.z - 1) {
        for (int r = t; r < B_ * N_; r += 256) {
            float bv = g_pval[r * 4 + 0];
            int   bj = g_pidx[r * 4 + 0];
#pragma unroll
            for (int q = 1; q < 4; q++) {
                float v = g_pval[r * 4 + q];
                if (v > bv) { bv = v; bj = g_pidx[r * 4 + q]; }  // idx grows with q
            }
            preds[r] = (float)bj;
        }
        __syncthreads();
        if (t == 0) g_cnt = 0;   // reset for next graph replay
    }
}

// ---------------------------------------------------------------------------
extern "C" void kernel_launch(void* const* d_in, const int* in_sizes, int n_in,
                              void* d_out, int out_size) {
    const float* x    = (const float*)d_in[0];   // [8,128,256] float32
    const int*   mask = (const int*)d_in[1];     // [8,128] bool -> int32
    const float* W    = (const float*)d_in[2];   // [1,1023] float32
    const float* bias = (const float*)d_in[3];   // [1] float32
    float* out = (float*)d_out;

    const int nlog = B_ * N_ * N_;               // 131072
    float* preds = out + nlog;                   // [1024] as float

    dim3 grid(N_ / BN, N_ / BM, B_);             // (4,4,8) = 128 blocks
    pair_fused_kernel<<<grid, 256>>>(x, mask, W, bias, out, preds);
}